// round 5
// baseline (speedup 1.0000x reference)
#include <cuda_runtime.h>
#include <math.h>

#define Bk   8
#define Cc   512
#define Wd   64
#define Hd   32
#define HIDd 256
#define Gg   1280
#define WH   (Wd*Hd)        // 2048
#define MXP  (Bk*WH)        // 16384
#define NDIAG (Wd + Hd - 1) // 95
#define NBLK 144            // 16 hid-chunks x 9 row-groups
#define RG   9

// smem layout (floats): Ws[512][80] | scratch (A staging / reduction) | ptrs
#define WS_FLOATS (512*80)          // 40960
#define AS_PITCH  34
#define AS_BUF    (64*AS_PITCH)     // 2176
#define SCRATCH_FLOATS 4608         // >= 2*AS_BUF (4352) and >= red 4480
#define SMEM_BYTES ((WS_FLOATS + SCRATCH_FLOATS)*4 + 64*8)

typedef unsigned long long ull;

// ---------------- f32x2 helpers ----------------
__device__ __forceinline__ ull pack2(float lo, float hi) {
    ull r;
    asm("mov.b64 %0, {%1, %2};" : "=l"(r)
        : "r"(__float_as_uint(lo)), "r"(__float_as_uint(hi)));
    return r;
}
__device__ __forceinline__ void ffma2(ull& d, ull a, ull b) {
    asm("fma.rn.f32x2 %0, %1, %2, %0;" : "+l"(d) : "l"(a), "l"(b));
}
__device__ __forceinline__ float2 unpack2(ull v) {
    unsigned lo, hi;
    asm("mov.b64 {%0, %1}, %2;" : "=r"(lo), "=r"(hi) : "l"(v));
    return make_float2(__uint_as_float(lo), __uint_as_float(hi));
}

// ---------------- device scratch ----------------
__device__ float g_xp[(size_t)MXP * Gg];
__device__ float g_h [(size_t)WH * Bk * HIDd];      // (w,h,b,hid)
__device__ float g_c [(size_t)WH * Bk * HIDd];
__device__ float g_part[2 * 128 * HIDd];
__device__ float g_scale[HIDd];
__device__ float g_shift[HIDd];
__device__ unsigned g_cnt = 0;
__device__ unsigned g_gen = 0;

// ---------------- Kernel A: xp = x @ Wx + b (f32x2 packed rows) ----------------
__global__ __launch_bounds__(256) void xp_gemm(const float* __restrict__ x,
                                               const float* __restrict__ Wx,
                                               const float* __restrict__ bias) {
    __shared__ __align__(16) float As[16][128];
    __shared__ __align__(16) float Bs[16][64];
    const int bm  = blockIdx.y * 128;
    const int bn  = blockIdx.x * 64;
    const int tid = threadIdx.x;

    const int b   = bm >> 11;
    const int wh0 = bm & 2047;
    const float* xb = x + (size_t)b * Cc * WH + wh0;

    const int am  = tid & 127;
    const int ak  = tid >> 7;
    const int bkr = tid >> 4;
    const int bn4 = (tid & 15) * 4;
    const int tx  = tid & 15;
    const int ty  = tid >> 4;

    ull acc2[4][4];
#pragma unroll
    for (int i = 0; i < 4; i++)
#pragma unroll
        for (int j = 0; j < 4; j++) acc2[i][j] = 0ull;

    for (int k0 = 0; k0 < Cc; k0 += 16) {
#pragma unroll
        for (int j = 0; j < 8; j++) {
            int c = ak + j * 2;
            As[c][am] = xb[(size_t)(k0 + c) * WH + am];
        }
        *(float4*)&Bs[bkr][bn4] =
            *(const float4*)&Wx[(size_t)(k0 + bkr) * Gg + bn + bn4];
        __syncthreads();
#pragma unroll
        for (int kk = 0; kk < 16; kk++) {
            ull a2[4];
#pragma unroll
            for (int rp = 0; rp < 4; rp++)
                a2[rp] = *(const ull*)&As[kk][ty * 8 + 2 * rp];
            float4 bv = *(float4*)&Bs[kk][tx * 4];
            ull b2[4] = {pack2(bv.x, bv.x), pack2(bv.y, bv.y),
                         pack2(bv.z, bv.z), pack2(bv.w, bv.w)};
#pragma unroll
            for (int rp = 0; rp < 4; rp++)
#pragma unroll
                for (int j = 0; j < 4; j++) ffma2(acc2[rp][j], a2[rp], b2[j]);
        }
        __syncthreads();
    }

    float4 bb4 = *(const float4*)&bias[bn + tx * 4];
#pragma unroll
    for (int rp = 0; rp < 4; rp++) {
        float2 c0 = unpack2(acc2[rp][0]);
        float2 c1 = unpack2(acc2[rp][1]);
        float2 c2 = unpack2(acc2[rp][2]);
        float2 c3 = unpack2(acc2[rp][3]);
        int m0 = bm + ty * 8 + 2 * rp;
        float4 r0 = make_float4(c0.x + bb4.x, c1.x + bb4.y, c2.x + bb4.z, c3.x + bb4.w);
        float4 r1 = make_float4(c0.y + bb4.x, c1.y + bb4.y, c2.y + bb4.z, c3.y + bb4.w);
        *(float4*)&g_xp[(size_t)m0 * Gg + bn + tx * 4]       = r0;
        *(float4*)&g_xp[(size_t)(m0 + 1) * Gg + bn + tx * 4] = r1;
    }
}

// ---------------- grid-wide software barrier ----------------
__device__ __forceinline__ void gsync() {
    __threadfence();
    __syncthreads();
    if (threadIdx.x == 0) {
        unsigned old = *(volatile unsigned*)&g_gen;
        if (atomicAdd(&g_cnt, 1u) == NBLK - 1) {
            g_cnt = 0;
            __threadfence();
            *(volatile unsigned*)&g_gen = old + 1;
        } else {
            while (*(volatile unsigned*)&g_gen == old) { }
        }
        __threadfence();
    }
    __syncthreads();
}

// ---------------- persistent fused MD-LSTM recurrence (f32x2) ----------------
// Block bid: nb = bid&15 (16 hid cols), rg = bid>>4 (9 row groups).
// Ws[512][80]: Ws[kk][g*16+t] = Wh(kk)[g*256+nb*16+t].
// 256 thr = 8 tn (2 cols each) x 32 tm. Row-pairs P=ceil(mt2/2)<=15;
// K split across S = pow2, S*P<=32, S<=8; 8 K-chunks of 64.
__global__ __launch_bounds__(256, 1) void mdlstm_persist(const float* __restrict__ Wh1,
                                                         const float* __restrict__ Wh2) {
    extern __shared__ float sm[];
    float* Ws = sm;
    float* Asm = sm + WS_FLOATS;
    const float** pls = (const float**)(sm + WS_FLOATS + SCRATCH_FLOATS);
    const float** pus = pls + 32;

    const int tid = threadIdx.x;
    const int bid = blockIdx.x;
    const int nb  = bid & 15;
    const int rg  = bid >> 4;

    // one-time weight preload
    for (int i = tid; i < WS_FLOATS; i += 256) {
        int kk = i / 80, c = i - kk * 80;
        int g = c >> 4, t = c & 15;
        int col = g * 256 + nb * 16 + t;
        Ws[i] = (kk < 256) ? Wh1[(size_t)kk * Gg + col]
                           : Wh2[(size_t)(kk - 256) * Gg + col];
    }

    const int tn = tid & 7;            // 2 cols: 2*tn, 2*tn+1 within 16-wide chunk
    const int tm = tid >> 3;           // 0..31
    const int srow = tid >> 3;         // staging row 0..31
    const int skq  = (tid & 7) * 8;    // staging 8 consecutive k

    for (int d = 0; d < NDIAG; d++) {
        int w_lo = d - (Hd - 1); if (w_lo < 0) w_lo = 0;
        int w_hi = (d < Wd - 1) ? d : (Wd - 1);
        int M = (w_hi - w_lo + 1) * Bk;
        int mt2 = (M + RG - 1) / RG;
        int r0 = rg * mt2;

        if (r0 < M) {
            int P = (mt2 + 1) >> 1;
            int S = 1;
            while (2 * S * P <= 32 && S < 8) S <<= 1;
            int pair  = tm % P;
            int slice = tm / P;
            bool active = (slice < S);
            int cw = 8 / S;
            int c_lo = active ? slice * cw : 0;
            int c_hi = active ? c_lo + cw : 0;

            if (tid < 32) {
                const float* pl = nullptr;
                const float* pu = nullptr;
                int gr = r0 + tid;
                if (tid < mt2 && gr < M) {
                    int ci = gr >> 3, b = gr & 7;
                    int w = w_lo + ci, h = d - w;
                    if (h > 0) pl = g_h + ((size_t)((w * Hd + (h - 1)) * Bk + b)) * HIDd;
                    if (w > 0) pu = g_h + ((size_t)(((w - 1) * Hd + h) * Bk + b)) * HIDd;
                }
                pls[tid] = pl;
                pus[tid] = pu;
            }
            __syncthreads();

            ull acc2[2][5];
#pragma unroll
            for (int i = 0; i < 2; i++)
#pragma unroll
                for (int g = 0; g < 5; g++) acc2[i][g] = 0ull;

            // stage chunk 0
            {
                const float* p = pls[srow];
                float4 v0 = {0,0,0,0}, v1 = {0,0,0,0};
                if (p) { v0 = *(const float4*)(p + skq); v1 = *(const float4*)(p + skq + 4); }
                float* Ab = Asm;
                Ab[(skq+0)*AS_PITCH + srow] = v0.x; Ab[(skq+1)*AS_PITCH + srow] = v0.y;
                Ab[(skq+2)*AS_PITCH + srow] = v0.z; Ab[(skq+3)*AS_PITCH + srow] = v0.w;
                Ab[(skq+4)*AS_PITCH + srow] = v1.x; Ab[(skq+5)*AS_PITCH + srow] = v1.y;
                Ab[(skq+6)*AS_PITCH + srow] = v1.z; Ab[(skq+7)*AS_PITCH + srow] = v1.w;
            }
            __syncthreads();

            for (int c = 0; c < 8; c++) {
                float4 v0 = {0,0,0,0}, v1 = {0,0,0,0};
                if (c < 7) {
                    const float* p = (c + 1 < 4) ? pls[srow] : pus[srow];
                    int koff = ((c + 1) & 3) * 64 + skq;
                    if (p) { v0 = *(const float4*)(p + koff); v1 = *(const float4*)(p + koff + 4); }
                }
                if (active && c >= c_lo && c < c_hi) {
                    const float* Acur = Asm + (c & 1) * AS_BUF;
#pragma unroll 8
                    for (int kk = 0; kk < 64; kk++) {
                        float2 ar = *(const float2*)&Acur[kk * AS_PITCH + 2 * pair];
                        ull a0 = pack2(ar.x, ar.x);
                        ull a1 = pack2(ar.y, ar.y);
                        const float* wrow = Ws + (c * 64 + kk) * 80 + 2 * tn;
                        ull b0 = *(const ull*)(wrow);
                        ull b1 = *(const ull*)(wrow + 16);
                        ull b2 = *(const ull*)(wrow + 32);
                        ull b3 = *(const ull*)(wrow + 48);
                        ull b4 = *(const ull*)(wrow + 64);
                        ffma2(acc2[0][0], a0, b0); ffma2(acc2[0][1], a0, b1);
                        ffma2(acc2[0][2], a0, b2); ffma2(acc2[0][3], a0, b3);
                        ffma2(acc2[0][4], a0, b4);
                        ffma2(acc2[1][0], a1, b0); ffma2(acc2[1][1], a1, b1);
                        ffma2(acc2[1][2], a1, b2); ffma2(acc2[1][3], a1, b3);
                        ffma2(acc2[1][4], a1, b4);
                    }
                }
                if (c < 7) {
                    float* Ab = Asm + ((c + 1) & 1) * AS_BUF;
                    Ab[(skq+0)*AS_PITCH + srow] = v0.x; Ab[(skq+1)*AS_PITCH + srow] = v0.y;
                    Ab[(skq+2)*AS_PITCH + srow] = v0.z; Ab[(skq+3)*AS_PITCH + srow] = v0.w;
                    Ab[(skq+4)*AS_PITCH + srow] = v1.x; Ab[(skq+5)*AS_PITCH + srow] = v1.y;
                    Ab[(skq+6)*AS_PITCH + srow] = v1.z; Ab[(skq+7)*AS_PITCH + srow] = v1.w;
                    __syncthreads();
                }
            }

            float2 av[2][5];
#pragma unroll
            for (int i = 0; i < 2; i++)
#pragma unroll
                for (int g = 0; g < 5; g++) av[i][g] = unpack2(acc2[i][g]);

            // cross-slice reduction
            if (S > 1) {
                __syncthreads();
                float2* red = (float2*)Asm;
                if (active && slice > 0) {
                    float2* dst = red + ((slice - 1) * P + pair) * 80 + tn * 10;
#pragma unroll
                    for (int i = 0; i < 2; i++)
#pragma unroll
                        for (int g = 0; g < 5; g++) dst[i * 5 + g] = av[i][g];
                }
                __syncthreads();
                if (slice == 0) {
                    for (int s = 1; s < S; s++) {
                        const float2* src = red + ((s - 1) * P + pair) * 80 + tn * 10;
#pragma unroll
                        for (int i = 0; i < 2; i++)
#pragma unroll
                            for (int g = 0; g < 5; g++) {
                                float2 v = src[i * 5 + g];
                                av[i][g].x += v.x;
                                av[i][g].y += v.y;
                            }
                    }
                }
            }

            // fused LSTM pointwise (2 cols per thread)
            if (slice == 0) {
                const int hid0 = nb * 16 + 2 * tn;
#pragma unroll
                for (int i = 0; i < 2; i++) {
                    int lr = 2 * pair + i;
                    int gr = r0 + lr;
                    if (lr < mt2 && gr < M) {
                        int ci = gr >> 3, b = gr & 7;
                        int w = w_lo + ci, h = d - w;

                        const float* xg = g_xp + ((size_t)(b * WH + w * Hd + h)) * Gg;
                        float2 xi  = *(const float2*)&xg[hid0];
                        float2 xf1 = *(const float2*)&xg[HIDd + hid0];
                        float2 xf2 = *(const float2*)&xg[2 * HIDd + hid0];
                        float2 xo  = *(const float2*)&xg[3 * HIDd + hid0];
                        float2 xc  = *(const float2*)&xg[4 * HIDd + hid0];

                        float2 cl = make_float2(0.f, 0.f), cu = make_float2(0.f, 0.f);
                        if (h > 0) cl = *(const float2*)&g_c[((size_t)((w * Hd + (h - 1)) * Bk + b)) * HIDd + hid0];
                        if (w > 0) cu = *(const float2*)&g_c[((size_t)(((w - 1) * Hd + h) * Bk + b)) * HIDd + hid0];

                        float2 cc, hv;
                        {
                            float gi  = av[i][0].x + xi.x;
                            float gf1 = av[i][1].x + xf1.x;
                            float gf2 = av[i][2].x + xf2.x;
                            float go  = av[i][3].x + xo.x;
                            float gc  = av[i][4].x + xc.x;
                            float i_ = 1.f / (1.f + expf(-gi));
                            float f1 = 1.f / (1.f + expf(-gf1));
                            float f2 = 1.f / (1.f + expf(-gf2));
                            float o_ = 1.f / (1.f + expf(-go));
                            float cand = tanhf(gc);
                            cc.x = i_ * cand + f1 * cl.x + f2 * cu.x;
                            hv.x = o_ * tanhf(cc.x);
                        }
                        {
                            float gi  = av[i][0].y + xi.y;
                            float gf1 = av[i][1].y + xf1.y;
                            float gf2 = av[i][2].y + xf2.y;
                            float go  = av[i][3].y + xo.y;
                            float gc  = av[i][4].y + xc.y;
                            float i_ = 1.f / (1.f + expf(-gi));
                            float f1 = 1.f / (1.f + expf(-gf1));
                            float f2 = 1.f / (1.f + expf(-gf2));
                            float o_ = 1.f / (1.f + expf(-go));
                            float cand = tanhf(gc);
                            cc.y = i_ * cand + f1 * cl.y + f2 * cu.y;
                            hv.y = o_ * tanhf(cc.y);
                        }

                        size_t oidx = ((size_t)((w * Hd + h) * Bk + b)) * HIDd + hid0;
                        *(float2*)&g_c[oidx] = cc;
                        *(float2*)&g_h[oidx] = hv;
                    }
                }
            }
        }

        gsync();
    }
}

// ---------------- BN stats ----------------
__global__ __launch_bounds__(256) void bn_reduce1() {
    const int t = threadIdx.x;
    const size_t r0 = (size_t)blockIdx.x * 128;
    float s = 0.f, s2 = 0.f;
    for (int r = 0; r < 128; r++) {
        float v = g_h[(r0 + r) * HIDd + t];
        s += v;
        s2 += v * v;
    }
    g_part[blockIdx.x * HIDd + t] = s;
    g_part[128 * HIDd + blockIdx.x * HIDd + t] = s2;
}

__global__ __launch_bounds__(256) void bn_reduce2(const float* __restrict__ gamma,
                                                  const float* __restrict__ beta) {
    const int t = threadIdx.x;
    float s0 = 0.f, s1 = 0.f, q0 = 0.f, q1 = 0.f;
#pragma unroll 4
    for (int i = 0; i < 128; i += 2) {
        s0 += g_part[i * HIDd + t];
        s1 += g_part[(i + 1) * HIDd + t];
        q0 += g_part[128 * HIDd + i * HIDd + t];
        q1 += g_part[128 * HIDd + (i + 1) * HIDd + t];
    }
    float s = s0 + s1, s2 = q0 + q1;
    const float invn = 1.f / (float)MXP;
    float mean = s * invn;
    float var  = s2 * invn - mean * mean;
    float sc   = gamma[t] * rsqrtf(var + 1e-5f);
    g_scale[t] = sc;
    g_shift[t] = beta[t] - mean * sc;
}

// ---------------- final writeout (smem transpose, coalesced both sides) ----------------
__global__ __launch_bounds__(256) void writeout(float* __restrict__ out) {
    __shared__ float t[32][257];
    const int bw = blockIdx.x;          // b*64 + w
    const int b  = bw >> 6;
    const int w  = bw & 63;
    const int tid = threadIdx.x;
    const int ch8 = tid >> 5;           // 0..7
    const int hl  = tid & 31;

    // pass 1: state -> out (tanh-bn) + state copy
    for (int hh = 0; hh < 32; hh++)
        t[hh][tid] = g_h[((size_t)((w * Hd + hh) * Bk + b)) * HIDd + tid];
    __syncthreads();
    for (int c0 = 0; c0 < 256; c0 += 8) {
        int ch = c0 + ch8;
        float v = t[hl][ch];
        size_t oi = (((size_t)b * HIDd + ch) * Wd + w) * Hd + hl;
        out[oi] = tanhf(v * g_scale[ch] + g_shift[ch]);
        out[(size_t)MXP * HIDd + oi] = v;
    }
    __syncthreads();

    // pass 2: cell copy
    for (int hh = 0; hh < 32; hh++)
        t[hh][tid] = g_c[((size_t)((w * Hd + hh) * Bk + b)) * HIDd + tid];
    __syncthreads();
    for (int c0 = 0; c0 < 256; c0 += 8) {
        int ch = c0 + ch8;
        size_t oi = (((size_t)b * HIDd + ch) * Wd + w) * Hd + hl;
        out[(size_t)2 * MXP * HIDd + oi] = t[hl][ch];
    }
}

// ---------------- launch ----------------
extern "C" void kernel_launch(void* const* d_in, const int* in_sizes, int n_in,
                              void* d_out, int out_size) {
    const float* x     = (const float*)d_in[0];
    const float* Wx    = (const float*)d_in[1];
    const float* Wh1   = (const float*)d_in[2];
    const float* Wh2   = (const float*)d_in[3];
    const float* bias  = (const float*)d_in[4];
    const float* gamma = (const float*)d_in[5];
    const float* beta  = (const float*)d_in[6];
    float* out = (float*)d_out;

    cudaFuncSetAttribute(mdlstm_persist,
                         cudaFuncAttributeMaxDynamicSharedMemorySize, SMEM_BYTES);

    xp_gemm<<<dim3(Gg / 64, MXP / 128), 256>>>(x, Wx, bias);
    mdlstm_persist<<<NBLK, 256, SMEM_BYTES>>>(Wh1, Wh2);
    bn_reduce1<<<128, 256>>>();
    bn_reduce2<<<1, 256>>>(gamma, beta);
    writeout<<<Bk * Wd, 256>>>(out);
}

// round 7
// speedup vs baseline: 1.5377x; 1.5377x over previous
#include <cuda_runtime.h>
#include <math.h>

#define Bk   8
#define Cc   512
#define Wd   64
#define Hd   32
#define HIDd 256
#define Gg   1280
#define WH   (Wd*Hd)        // 2048
#define MXP  (Bk*WH)        // 16384
#define NDIAG (Wd + Hd - 1) // 95
#define NBLK 144            // 16 hid-chunks x 9 row-groups
#define RG   9

// smem layout (floats): Ws[512][80] | scratch (A staging / reduction) | ptrs
#define WS_FLOATS (512*80)          // 40960
#define AS_PITCH  34
#define AS_BUF    (64*AS_PITCH)     // 2176
#define SCRATCH_FLOATS 4608         // >= 2*AS_BUF (4352), >= reduction (<=2400)
#define SMEM_BYTES ((WS_FLOATS + SCRATCH_FLOATS)*4 + 64*8)

// ---------------- device scratch ----------------
__device__ float g_xp[(size_t)MXP * Gg];
__device__ float g_h [(size_t)WH * Bk * HIDd];      // (w,h,b,hid)
__device__ float g_c [(size_t)WH * Bk * HIDd];
__device__ float g_part[2 * 128 * HIDd];
__device__ float g_scale[HIDd];
__device__ float g_shift[HIDd];
__device__ unsigned g_cnt = 0;
__device__ unsigned g_gen = 0;

// ---------------- Kernel A: xp = x @ Wx + b (scalar, proven) ----------------
__global__ __launch_bounds__(256) void xp_gemm(const float* __restrict__ x,
                                               const float* __restrict__ Wx,
                                               const float* __restrict__ bias) {
    __shared__ float As[16][128];
    __shared__ float Bs[16][64];
    const int bm  = blockIdx.y * 128;
    const int bn  = blockIdx.x * 64;
    const int tid = threadIdx.x;

    const int b   = bm >> 11;
    const int wh0 = bm & 2047;
    const float* xb = x + (size_t)b * Cc * WH + wh0;

    const int am  = tid & 127;
    const int ak  = tid >> 7;
    const int bkr = tid >> 4;
    const int bn4 = (tid & 15) * 4;
    const int tx  = tid & 15;
    const int ty  = tid >> 4;

    float acc[8][4];
#pragma unroll
    for (int i = 0; i < 8; i++)
#pragma unroll
        for (int j = 0; j < 4; j++) acc[i][j] = 0.f;

    for (int k0 = 0; k0 < Cc; k0 += 16) {
#pragma unroll
        for (int j = 0; j < 8; j++) {
            int c = ak + j * 2;
            As[c][am] = xb[(size_t)(k0 + c) * WH + am];
        }
        *(float4*)&Bs[bkr][bn4] =
            *(const float4*)&Wx[(size_t)(k0 + bkr) * Gg + bn + bn4];
        __syncthreads();
#pragma unroll
        for (int kk = 0; kk < 16; kk++) {
            float4 a0 = *(float4*)&As[kk][ty * 8];
            float4 a1 = *(float4*)&As[kk][ty * 8 + 4];
            float4 bv = *(float4*)&Bs[kk][tx * 4];
            float aa[8] = {a0.x, a0.y, a0.z, a0.w, a1.x, a1.y, a1.z, a1.w};
            float bb[4] = {bv.x, bv.y, bv.z, bv.w};
#pragma unroll
            for (int i = 0; i < 8; i++)
#pragma unroll
                for (int j = 0; j < 4; j++) acc[i][j] += aa[i] * bb[j];
        }
        __syncthreads();
    }

    float4 bb4 = *(const float4*)&bias[bn + tx * 4];
#pragma unroll
    for (int i = 0; i < 8; i++) {
        int m = bm + ty * 8 + i;
        float4 v;
        v.x = acc[i][0] + bb4.x;
        v.y = acc[i][1] + bb4.y;
        v.z = acc[i][2] + bb4.z;
        v.w = acc[i][3] + bb4.w;
        *(float4*)&g_xp[(size_t)m * Gg + bn + tx * 4] = v;
    }
}

// ---------------- grid-wide software barrier ----------------
__device__ __forceinline__ void gsync() {
    __threadfence();
    __syncthreads();
    if (threadIdx.x == 0) {
        unsigned old = *(volatile unsigned*)&g_gen;
        if (atomicAdd(&g_cnt, 1u) == NBLK - 1) {
            g_cnt = 0;
            __threadfence();
            *(volatile unsigned*)&g_gen = old + 1;
        } else {
            while (*(volatile unsigned*)&g_gen == old) { }
        }
        __threadfence();
    }
    __syncthreads();
}

// ---------------- persistent fused MD-LSTM recurrence (scalar, 2 cols/thread) ----------------
// Block bid: nb = bid&15 (16 hid cols), rg = bid>>4 (9 row groups).
// Ws[512][80]: Ws[kk][g*16+t] = Wh(kk)[g*256+nb*16+t].
// 256 thr = 8 tn (cols 2tn,2tn+1) x 32 tm. Row-pairs P=ceil(mt2/2)<=15;
// K split across S = pow2, 2*S*P<=32, S<=8; 8 K-chunks of 64 (full diag: S=2).
__global__ __launch_bounds__(256, 1) void mdlstm_persist(const float* __restrict__ Wh1,
                                                         const float* __restrict__ Wh2) {
    extern __shared__ float sm[];
    float* Ws = sm;
    float* Asm = sm + WS_FLOATS;
    const float** pls = (const float**)(sm + WS_FLOATS + SCRATCH_FLOATS);
    const float** pus = pls + 32;

    const int tid = threadIdx.x;
    const int bid = blockIdx.x;
    const int nb  = bid & 15;
    const int rg  = bid >> 4;

    // one-time weight preload
    for (int i = tid; i < WS_FLOATS; i += 256) {
        int kk = i / 80, c = i - kk * 80;
        int g = c >> 4, t = c & 15;
        int col = g * 256 + nb * 16 + t;
        Ws[i] = (kk < 256) ? Wh1[(size_t)kk * Gg + col]
                           : Wh2[(size_t)(kk - 256) * Gg + col];
    }

    const int tn = tid & 7;            // cols 2tn, 2tn+1 within 16-wide chunk
    const int tm = tid >> 3;           // 0..31
    const int srow = tid >> 3;         // staging row 0..31
    const int skq  = (tid & 7) * 8;    // staging 8 consecutive k

    for (int d = 0; d < NDIAG; d++) {
        int w_lo = d - (Hd - 1); if (w_lo < 0) w_lo = 0;
        int w_hi = (d < Wd - 1) ? d : (Wd - 1);
        int M = (w_hi - w_lo + 1) * Bk;
        int mt2 = (M + RG - 1) / RG;
        int r0 = rg * mt2;

        if (r0 < M) {
            int P = (mt2 + 1) >> 1;
            int S = 1;
            while (2 * S * P <= 32 && S < 8) S <<= 1;
            int pair  = tm % P;
            int slice = tm / P;
            bool active = (slice < S);
            int cw = 8 / S;
            int c_lo = active ? slice * cw : 0;
            int c_hi = active ? c_lo + cw : 0;

            if (tid < 32) {
                const float* pl = nullptr;
                const float* pu = nullptr;
                int gr = r0 + tid;
                if (tid < mt2 && gr < M) {
                    int ci = gr >> 3, b = gr & 7;
                    int w = w_lo + ci, h = d - w;
                    if (h > 0) pl = g_h + ((size_t)((w * Hd + (h - 1)) * Bk + b)) * HIDd;
                    if (w > 0) pu = g_h + ((size_t)(((w - 1) * Hd + h) * Bk + b)) * HIDd;
                }
                pls[tid] = pl;
                pus[tid] = pu;
            }
            __syncthreads();

            // acc[row][gate][col]
            float acc[2][5][2];
#pragma unroll
            for (int i = 0; i < 2; i++)
#pragma unroll
                for (int g = 0; g < 5; g++) { acc[i][g][0] = 0.f; acc[i][g][1] = 0.f; }

            // stage chunk 0
            {
                const float* p = pls[srow];
                float4 v0 = {0,0,0,0}, v1 = {0,0,0,0};
                if (p) { v0 = *(const float4*)(p + skq); v1 = *(const float4*)(p + skq + 4); }
                float* Ab = Asm;
                Ab[(skq+0)*AS_PITCH + srow] = v0.x; Ab[(skq+1)*AS_PITCH + srow] = v0.y;
                Ab[(skq+2)*AS_PITCH + srow] = v0.z; Ab[(skq+3)*AS_PITCH + srow] = v0.w;
                Ab[(skq+4)*AS_PITCH + srow] = v1.x; Ab[(skq+5)*AS_PITCH + srow] = v1.y;
                Ab[(skq+6)*AS_PITCH + srow] = v1.z; Ab[(skq+7)*AS_PITCH + srow] = v1.w;
            }
            __syncthreads();

            for (int c = 0; c < 8; c++) {
                float4 v0 = {0,0,0,0}, v1 = {0,0,0,0};
                if (c < 7) {
                    const float* p = (c + 1 < 4) ? pls[srow] : pus[srow];
                    int koff = ((c + 1) & 3) * 64 + skq;
                    if (p) { v0 = *(const float4*)(p + koff); v1 = *(const float4*)(p + koff + 4); }
                }
                if (active && c >= c_lo && c < c_hi) {
                    const float* Acur = Asm + (c & 1) * AS_BUF;
#pragma unroll 8
                    for (int kk = 0; kk < 64; kk++) {
                        float2 a = *(const float2*)&Acur[kk * AS_PITCH + 2 * pair];
                        const float* wrow = Ws + (c * 64 + kk) * 80 + 2 * tn;
                        float2 b0 = *(const float2*)(wrow);
                        float2 b1 = *(const float2*)(wrow + 16);
                        float2 b2 = *(const float2*)(wrow + 32);
                        float2 b3 = *(const float2*)(wrow + 48);
                        float2 b4 = *(const float2*)(wrow + 64);
                        acc[0][0][0] += a.x * b0.x; acc[0][0][1] += a.x * b0.y;
                        acc[0][1][0] += a.x * b1.x; acc[0][1][1] += a.x * b1.y;
                        acc[0][2][0] += a.x * b2.x; acc[0][2][1] += a.x * b2.y;
                        acc[0][3][0] += a.x * b3.x; acc[0][3][1] += a.x * b3.y;
                        acc[0][4][0] += a.x * b4.x; acc[0][4][1] += a.x * b4.y;
                        acc[1][0][0] += a.y * b0.x; acc[1][0][1] += a.y * b0.y;
                        acc[1][1][0] += a.y * b1.x; acc[1][1][1] += a.y * b1.y;
                        acc[1][2][0] += a.y * b2.x; acc[1][2][1] += a.y * b2.y;
                        acc[1][3][0] += a.y * b3.x; acc[1][3][1] += a.y * b3.y;
                        acc[1][4][0] += a.y * b4.x; acc[1][4][1] += a.y * b4.y;
                    }
                }
                if (c < 7) {
                    float* Ab = Asm + ((c + 1) & 1) * AS_BUF;
                    Ab[(skq+0)*AS_PITCH + srow] = v0.x; Ab[(skq+1)*AS_PITCH + srow] = v0.y;
                    Ab[(skq+2)*AS_PITCH + srow] = v0.z; Ab[(skq+3)*AS_PITCH + srow] = v0.w;
                    Ab[(skq+4)*AS_PITCH + srow] = v1.x; Ab[(skq+5)*AS_PITCH + srow] = v1.y;
                    Ab[(skq+6)*AS_PITCH + srow] = v1.z; Ab[(skq+7)*AS_PITCH + srow] = v1.w;
                    __syncthreads();
                }
            }

            // cross-slice reduction
            if (S > 1) {
                __syncthreads();
                float* red = Asm;
                if (active && slice > 0) {
                    float* dst = red + ((slice - 1) * P + pair) * 160 + tn * 20;
#pragma unroll
                    for (int i = 0; i < 2; i++)
#pragma unroll
                        for (int g = 0; g < 5; g++) {
                            dst[(i * 5 + g) * 2]     = acc[i][g][0];
                            dst[(i * 5 + g) * 2 + 1] = acc[i][g][1];
                        }
                }
                __syncthreads();
                if (slice == 0) {
                    for (int s = 1; s < S; s++) {
                        const float* src = red + ((s - 1) * P + pair) * 160 + tn * 20;
#pragma unroll
                        for (int i = 0; i < 2; i++)
#pragma unroll
                            for (int g = 0; g < 5; g++) {
                                acc[i][g][0] += src[(i * 5 + g) * 2];
                                acc[i][g][1] += src[(i * 5 + g) * 2 + 1];
                            }
                    }
                }
            }

            // fused LSTM pointwise (2 cols per thread)
            if (slice == 0) {
                const int hid0 = nb * 16 + 2 * tn;
#pragma unroll
                for (int i = 0; i < 2; i++) {
                    int lr = 2 * pair + i;
                    int gr = r0 + lr;
                    if (lr < mt2 && gr < M) {
                        int ci = gr >> 3, b = gr & 7;
                        int w = w_lo + ci, h = d - w;

                        const float* xg = g_xp + ((size_t)(b * WH + w * Hd + h)) * Gg;
                        float2 xi  = *(const float2*)&xg[hid0];
                        float2 xf1 = *(const float2*)&xg[HIDd + hid0];
                        float2 xf2 = *(const float2*)&xg[2 * HIDd + hid0];
                        float2 xo  = *(const float2*)&xg[3 * HIDd + hid0];
                        float2 xc  = *(const float2*)&xg[4 * HIDd + hid0];

                        float2 cl = make_float2(0.f, 0.f), cu = make_float2(0.f, 0.f);
                        if (h > 0) cl = *(const float2*)&g_c[((size_t)((w * Hd + (h - 1)) * Bk + b)) * HIDd + hid0];
                        if (w > 0) cu = *(const float2*)&g_c[((size_t)(((w - 1) * Hd + h) * Bk + b)) * HIDd + hid0];

                        float2 cc, hv;
                        {
                            float gi  = acc[i][0][0] + xi.x;
                            float gf1 = acc[i][1][0] + xf1.x;
                            float gf2 = acc[i][2][0] + xf2.x;
                            float go  = acc[i][3][0] + xo.x;
                            float gc  = acc[i][4][0] + xc.x;
                            float i_ = 1.f / (1.f + expf(-gi));
                            float f1 = 1.f / (1.f + expf(-gf1));
                            float f2 = 1.f / (1.f + expf(-gf2));
                            float o_ = 1.f / (1.f + expf(-go));
                            float cand = tanhf(gc);
                            cc.x = i_ * cand + f1 * cl.x + f2 * cu.x;
                            hv.x = o_ * tanhf(cc.x);
                        }
                        {
                            float gi  = acc[i][0][1] + xi.y;
                            float gf1 = acc[i][1][1] + xf1.y;
                            float gf2 = acc[i][2][1] + xf2.y;
                            float go  = acc[i][3][1] + xo.y;
                            float gc  = acc[i][4][1] + xc.y;
                            float i_ = 1.f / (1.f + expf(-gi));
                            float f1 = 1.f / (1.f + expf(-gf1));
                            float f2 = 1.f / (1.f + expf(-gf2));
                            float o_ = 1.f / (1.f + expf(-go));
                            float cand = tanhf(gc);
                            cc.y = i_ * cand + f1 * cl.y + f2 * cu.y;
                            hv.y = o_ * tanhf(cc.y);
                        }

                        size_t oidx = ((size_t)((w * Hd + h) * Bk + b)) * HIDd + hid0;
                        *(float2*)&g_c[oidx] = cc;
                        *(float2*)&g_h[oidx] = hv;
                    }
                }
            }
        }

        gsync();
    }
}

// ---------------- BN stats ----------------
__global__ __launch_bounds__(256) void bn_reduce1() {
    const int t = threadIdx.x;
    const size_t r0 = (size_t)blockIdx.x * 128;
    float s = 0.f, s2 = 0.f;
    for (int r = 0; r < 128; r++) {
        float v = g_h[(r0 + r) * HIDd + t];
        s += v;
        s2 += v * v;
    }
    g_part[blockIdx.x * HIDd + t] = s;
    g_part[128 * HIDd + blockIdx.x * HIDd + t] = s2;
}

__global__ __launch_bounds__(256) void bn_reduce2(const float* __restrict__ gamma,
                                                  const float* __restrict__ beta) {
    const int t = threadIdx.x;
    float s0 = 0.f, s1 = 0.f, q0 = 0.f, q1 = 0.f;
#pragma unroll 4
    for (int i = 0; i < 128; i += 2) {
        s0 += g_part[i * HIDd + t];
        s1 += g_part[(i + 1) * HIDd + t];
        q0 += g_part[128 * HIDd + i * HIDd + t];
        q1 += g_part[128 * HIDd + (i + 1) * HIDd + t];
    }
    float s = s0 + s1, s2 = q0 + q1;
    const float invn = 1.f / (float)MXP;
    float mean = s * invn;
    float var  = s2 * invn - mean * mean;
    float sc   = gamma[t] * rsqrtf(var + 1e-5f);
    g_scale[t] = sc;
    g_shift[t] = beta[t] - mean * sc;
}

// ---------------- final writeout (smem transpose, coalesced both sides) ----------------
__global__ __launch_bounds__(256) void writeout(float* __restrict__ out) {
    __shared__ float t[32][257];
    const int bw = blockIdx.x;          // b*64 + w
    const int b  = bw >> 6;
    const int w  = bw & 63;
    const int tid = threadIdx.x;
    const int ch8 = tid >> 5;           // 0..7
    const int hl  = tid & 31;

    for (int hh = 0; hh < 32; hh++)
        t[hh][tid] = g_h[((size_t)((w * Hd + hh) * Bk + b)) * HIDd + tid];
    __syncthreads();
    for (int c0 = 0; c0 < 256; c0 += 8) {
        int ch = c0 + ch8;
        float v = t[hl][ch];
        size_t oi = (((size_t)b * HIDd + ch) * Wd + w) * Hd + hl;
        out[oi] = tanhf(v * g_scale[ch] + g_shift[ch]);
        out[(size_t)MXP * HIDd + oi] = v;
    }
    __syncthreads();

    for (int hh = 0; hh < 32; hh++)
        t[hh][tid] = g_c[((size_t)((w * Hd + hh) * Bk + b)) * HIDd + tid];
    __syncthreads();
    for (int c0 = 0; c0 < 256; c0 += 8) {
        int ch = c0 + ch8;
        size_t oi = (((size_t)b * HIDd + ch) * Wd + w) * Hd + hl;
        out[(size_t)2 * MXP * HIDd + oi] = t[hl][ch];
    }
}

// ---------------- launch ----------------
extern "C" void kernel_launch(void* const* d_in, const int* in_sizes, int n_in,
                              void* d_out, int out_size) {
    const float* x     = (const float*)d_in[0];
    const float* Wx    = (const float*)d_in[1];
    const float* Wh1   = (const float*)d_in[2];
    const float* Wh2   = (const float*)d_in[3];
    const float* bias  = (const float*)d_in[4];
    const float* gamma = (const float*)d_in[5];
    const float* beta  = (const float*)d_in[6];
    float* out = (float*)d_out;

    cudaFuncSetAttribute(mdlstm_persist,
                         cudaFuncAttributeMaxDynamicSharedMemorySize, SMEM_BYTES);

    xp_gemm<<<dim3(Gg / 64, MXP / 128), 256>>>(x, Wx, bias);
    mdlstm_persist<<<NBLK, 256, SMEM_BYTES>>>(Wh1, Wh2);
    bn_reduce1<<<128, 256>>>();
    bn_reduce2<<<1, 256>>>(gamma, beta);
    writeout<<<Bk * Wd, 256>>>(out);
}

// round 10
// speedup vs baseline: 1.8398x; 1.1965x over previous
#include <cuda_runtime.h>
#include <math.h>

#define Bk   8
#define Cc   512
#define Wd   64
#define Hd   32
#define HIDd 256
#define Gg   1280
#define WH   (Wd*Hd)        // 2048
#define MXP  (Bk*WH)        // 16384
#define NDIAG (Wd + Hd - 1) // 95
#define NBLK 144            // 16 hid-chunks x 9 row-groups
#define RG   9

// smem layout (floats): Ws[512][80] | A[512][30]
#define WS_FLOATS (512*80)          // 40960 floats = 160KB
#define AP        30                // A row-pitch (even -> aligned LDS.64; rows needed <= 30)
#define A_FLOATS  (512*AP)          // 15360 floats = 60KB
#define SMEM_BYTES ((WS_FLOATS + A_FLOATS)*4)   // 225280 B

// ---------------- device scratch ----------------
__device__ float g_xp[(size_t)MXP * Gg];
__device__ float g_h [(size_t)WH * Bk * HIDd];      // (w,h,b,hid)
__device__ float g_c [(size_t)WH * Bk * HIDd];
__device__ float g_part[2 * 128 * HIDd];
__device__ float g_scale[HIDd];
__device__ float g_shift[HIDd];
__device__ unsigned g_cnt = 0;
__device__ unsigned g_gen = 0;

// ---------------- Kernel A: xp = x @ Wx + b (scalar, proven) ----------------
__global__ __launch_bounds__(256) void xp_gemm(const float* __restrict__ x,
                                               const float* __restrict__ Wx,
                                               const float* __restrict__ bias) {
    __shared__ float As[16][128];
    __shared__ float Bs[16][64];
    const int bm  = blockIdx.y * 128;
    const int bn  = blockIdx.x * 64;
    const int tid = threadIdx.x;

    const int b   = bm >> 11;
    const int wh0 = bm & 2047;
    const float* xb = x + (size_t)b * Cc * WH + wh0;

    const int am  = tid & 127;
    const int ak  = tid >> 7;
    const int bkr = tid >> 4;
    const int bn4 = (tid & 15) * 4;
    const int tx  = tid & 15;
    const int ty  = tid >> 4;

    float acc[8][4];
#pragma unroll
    for (int i = 0; i < 8; i++)
#pragma unroll
        for (int j = 0; j < 4; j++) acc[i][j] = 0.f;

    for (int k0 = 0; k0 < Cc; k0 += 16) {
#pragma unroll
        for (int j = 0; j < 8; j++) {
            int c = ak + j * 2;
            As[c][am] = xb[(size_t)(k0 + c) * WH + am];
        }
        *(float4*)&Bs[bkr][bn4] =
            *(const float4*)&Wx[(size_t)(k0 + bkr) * Gg + bn + bn4];
        __syncthreads();
#pragma unroll
        for (int kk = 0; kk < 16; kk++) {
            float4 a0 = *(float4*)&As[kk][ty * 8];
            float4 a1 = *(float4*)&As[kk][ty * 8 + 4];
            float4 bv = *(float4*)&Bs[kk][tx * 4];
            float aa[8] = {a0.x, a0.y, a0.z, a0.w, a1.x, a1.y, a1.z, a1.w};
            float bb[4] = {bv.x, bv.y, bv.z, bv.w};
#pragma unroll
            for (int i = 0; i < 8; i++)
#pragma unroll
                for (int j = 0; j < 4; j++) acc[i][j] += aa[i] * bb[j];
        }
        __syncthreads();
    }

    float4 bb4 = *(const float4*)&bias[bn + tx * 4];
#pragma unroll
    for (int i = 0; i < 8; i++) {
        int m = bm + ty * 8 + i;
        float4 v;
        v.x = acc[i][0] + bb4.x;
        v.y = acc[i][1] + bb4.y;
        v.z = acc[i][2] + bb4.z;
        v.w = acc[i][3] + bb4.w;
        *(float4*)&g_xp[(size_t)m * Gg + bn + tx * 4] = v;
    }
}

// ---------------- grid-wide software barrier ----------------
__device__ __forceinline__ void gsync() {
    __threadfence();
    __syncthreads();
    if (threadIdx.x == 0) {
        unsigned old = *(volatile unsigned*)&g_gen;
        if (atomicAdd(&g_cnt, 1u) == NBLK - 1) {
            g_cnt = 0;
            __threadfence();
            *(volatile unsigned*)&g_gen = old + 1;
        } else {
            while (*(volatile unsigned*)&g_gen == old) { }
        }
        __threadfence();
    }
    __syncthreads();
}

// ---------------- persistent fused MD-LSTM recurrence ----------------
// Block bid: nb = bid&15 (16 hid cols), rg = bid>>4 (9 row groups).
// Ws[512][80]: Ws[kk][g*16+t] = Wh(kk)[g*256+nb*16+t].
// A[512][30]: A[k][row] = neighbor h (k<256: left via Wh1 rows; k>=256: up),
// staged ONCE per diagonal. 256 thr = 16 tn x 16 tm (2 rows each).
// Row-pairs P=ceil(mt2/2)<=15; K split S=pow2, 2*S*P<=16, S<=8.
__global__ __launch_bounds__(256, 1) void mdlstm_persist(const float* __restrict__ Wh1,
                                                         const float* __restrict__ Wh2) {
    extern __shared__ float sm[];
    float* Ws  = sm;
    float* Asm = sm + WS_FLOATS;

    const int tid = threadIdx.x;
    const int bid = blockIdx.x;
    const int nb  = bid & 15;
    const int rg  = bid >> 4;

    // one-time weight preload
    for (int i = tid; i < WS_FLOATS; i += 256) {
        int kk = i / 80, c = i - kk * 80;
        int g = c >> 4, t = c & 15;
        int col = g * 256 + nb * 16 + t;
        Ws[i] = (kk < 256) ? Wh1[(size_t)kk * Gg + col]
                           : Wh2[(size_t)(kk - 256) * Gg + col];
    }

    const int tn   = tid & 15;         // hid col within 16-wide chunk
    const int tm   = tid >> 4;         // 0..15 (row pair / K-slice group)
    const int srow = tid >> 3;         // staging row 0..31 (rows >=30 idle)
    const int sq   = tid & 7;          // staging: 8 threads per row

    for (int d = 0; d < NDIAG; d++) {
        int w_lo = d - (Hd - 1); if (w_lo < 0) w_lo = 0;
        int w_hi = (d < Wd - 1) ? d : (Wd - 1);
        int M = (w_hi - w_lo + 1) * Bk;
        int mt2 = (M + RG - 1) / RG;
        int r0 = rg * mt2;

        if (r0 < M) {
            int P = (mt2 + 1) >> 1;
            int S = 1;
            while (2 * S * P <= 16 && S < 8) S <<= 1;
            int pair  = tm % P;
            int slice = tm / P;
            bool active = (slice < S);
            int kpt = 512 / S;

            // ---- one-shot A staging: rows 0..29, k 0..511 ----
            if (srow < AP) {
                const float* pl = nullptr;
                const float* pu = nullptr;
                int gr = r0 + srow;
                if (srow < mt2 && gr < M) {
                    int ci = gr >> 3, b = gr & 7;
                    int w = w_lo + ci, h = d - w;
                    if (h > 0) pl = g_h + ((size_t)((w * Hd + (h - 1)) * Bk + b)) * HIDd;
                    if (w > 0) pu = g_h + ((size_t)(((w - 1) * Hd + h) * Bk + b)) * HIDd;
                }
#pragma unroll
                for (int j = 0; j < 16; j++) {
                    int k = 4 * (sq + 8 * j);
                    float4 v = make_float4(0.f, 0.f, 0.f, 0.f);
                    if (k < 256) { if (pl) v = *(const float4*)(pl + k); }
                    else         { if (pu) v = *(const float4*)(pu + k - 256); }
                    Asm[(k + 0) * AP + srow] = v.x;
                    Asm[(k + 1) * AP + srow] = v.y;
                    Asm[(k + 2) * AP + srow] = v.z;
                    Asm[(k + 3) * AP + srow] = v.w;
                }
            }
            __syncthreads();

            float acc[2][5];
#pragma unroll
            for (int i = 0; i < 2; i++)
#pragma unroll
                for (int g = 0; g < 5; g++) acc[i][g] = 0.f;

            if (active) {
                int k_lo = slice * kpt;
                int k_hi = k_lo + kpt;
#pragma unroll 8
                for (int k = k_lo; k < k_hi; k++) {
                    float2 a = *(const float2*)&Asm[k * AP + 2 * pair];
                    const float* wrow = Ws + k * 80 + tn;
                    float b0 = wrow[0];
                    float b1 = wrow[16];
                    float b2 = wrow[32];
                    float b3 = wrow[48];
                    float b4 = wrow[64];
                    acc[0][0] += a.x * b0; acc[0][1] += a.x * b1; acc[0][2] += a.x * b2;
                    acc[0][3] += a.x * b3; acc[0][4] += a.x * b4;
                    acc[1][0] += a.y * b0; acc[1][1] += a.y * b1; acc[1][2] += a.y * b2;
                    acc[1][3] += a.y * b3; acc[1][4] += a.y * b4;
                }
            }

            // cross-slice reduction (reuse A region after compute done)
            if (S > 1) {
                __syncthreads();
                float* red = Asm;
                if (active && slice > 0) {
                    float* dst = red + ((slice - 1) * P + pair) * 160 + tn;
#pragma unroll
                    for (int i = 0; i < 2; i++)
#pragma unroll
                        for (int g = 0; g < 5; g++) dst[(i * 5 + g) * 16] = acc[i][g];
                }
                __syncthreads();
                if (slice == 0) {
                    for (int s = 1; s < S; s++) {
                        const float* src = red + ((s - 1) * P + pair) * 160 + tn;
#pragma unroll
                        for (int i = 0; i < 2; i++)
#pragma unroll
                            for (int g = 0; g < 5; g++) acc[i][g] += src[(i * 5 + g) * 16];
                    }
                }
            }

            // fused LSTM pointwise (slice-0 threads own full rows)
            if (slice == 0) {
                const int hid = nb * 16 + tn;
#pragma unroll
                for (int i = 0; i < 2; i++) {
                    int lr = 2 * pair + i;
                    int gr = r0 + lr;
                    if (lr < mt2 && gr < M) {
                        int ci = gr >> 3, b = gr & 7;
                        int w = w_lo + ci, h = d - w;

                        const float* xg = g_xp + ((size_t)(b * WH + w * Hd + h)) * Gg;
                        float gi  = acc[i][0] + xg[hid];
                        float gf1 = acc[i][1] + xg[HIDd + hid];
                        float gf2 = acc[i][2] + xg[2 * HIDd + hid];
                        float go  = acc[i][3] + xg[3 * HIDd + hid];
                        float gc  = acc[i][4] + xg[4 * HIDd + hid];

                        float i_ = 1.f / (1.f + expf(-gi));
                        float f1 = 1.f / (1.f + expf(-gf1));
                        float f2 = 1.f / (1.f + expf(-gf2));
                        float o_ = 1.f / (1.f + expf(-go));
                        float cand = tanhf(gc);

                        float cl = (h > 0) ? g_c[((size_t)((w * Hd + (h - 1)) * Bk + b)) * HIDd + hid] : 0.f;
                        float cu = (w > 0) ? g_c[((size_t)(((w - 1) * Hd + h) * Bk + b)) * HIDd + hid] : 0.f;

                        float cc = i_ * cand + f1 * cl + f2 * cu;
                        float hv = o_ * tanhf(cc);

                        size_t oidx = ((size_t)((w * Hd + h) * Bk + b)) * HIDd + hid;
                        g_c[oidx] = cc;
                        g_h[oidx] = hv;
                    }
                }
            }
        }

        gsync();
    }
}

// ---------------- BN stats ----------------
__global__ __launch_bounds__(256) void bn_reduce1() {
    const int t = threadIdx.x;
    const size_t r0 = (size_t)blockIdx.x * 128;
    float s = 0.f, s2 = 0.f;
    for (int r = 0; r < 128; r++) {
        float v = g_h[(r0 + r) * HIDd + t];
        s += v;
        s2 += v * v;
    }
    g_part[blockIdx.x * HIDd + t] = s;
    g_part[128 * HIDd + blockIdx.x * HIDd + t] = s2;
}

__global__ __launch_bounds__(256) void bn_reduce2(const float* __restrict__ gamma,
                                                  const float* __restrict__ beta) {
    const int t = threadIdx.x;
    float s0 = 0.f, s1 = 0.f, q0 = 0.f, q1 = 0.f;
#pragma unroll 4
    for (int i = 0; i < 128; i += 2) {
        s0 += g_part[i * HIDd + t];
        s1 += g_part[(i + 1) * HIDd + t];
        q0 += g_part[128 * HIDd + i * HIDd + t];
        q1 += g_part[128 * HIDd + (i + 1) * HIDd + t];
    }
    float s = s0 + s1, s2 = q0 + q1;
    const float invn = 1.f / (float)MXP;
    float mean = s * invn;
    float var  = s2 * invn - mean * mean;
    float sc   = gamma[t] * rsqrtf(var + 1e-5f);
    g_scale[t] = sc;
    g_shift[t] = beta[t] - mean * sc;
}

// ---------------- final writeout (smem transpose, coalesced both sides) ----------------
__global__ __launch_bounds__(256) void writeout(float* __restrict__ out) {
    __shared__ float t[32][257];
    const int bw = blockIdx.x;          // b*64 + w
    const int b  = bw >> 6;
    const int w  = bw & 63;
    const int tid = threadIdx.x;
    const int ch8 = tid >> 5;           // 0..7
    const int hl  = tid & 31;

    for (int hh = 0; hh < 32; hh++)
        t[hh][tid] = g_h[((size_t)((w * Hd + hh) * Bk + b)) * HIDd + tid];
    __syncthreads();
    for (int c0 = 0; c0 < 256; c0 += 8) {
        int ch = c0 + ch8;
        float v = t[hl][ch];
        size_t oi = (((size_t)b * HIDd + ch) * Wd + w) * Hd + hl;
        out[oi] = tanhf(v * g_scale[ch] + g_shift[ch]);
        out[(size_t)MXP * HIDd + oi] = v;
    }
    __syncthreads();

    for (int hh = 0; hh < 32; hh++)
        t[hh][tid] = g_c[((size_t)((w * Hd + hh) * Bk + b)) * HIDd + tid];
    __syncthreads();
    for (int c0 = 0; c0 < 256; c0 += 8) {
        int ch = c0 + ch8;
        size_t oi = (((size_t)b * HIDd + ch) * Wd + w) * Hd + hl;
        out[(size_t)2 * MXP * HIDd + oi] = t[hl][ch];
    }
}

// ---------------- launch ----------------
extern "C" void kernel_launch(void* const* d_in, const int* in_sizes, int n_in,
                              void* d_out, int out_size) {
    const float* x     = (const float*)d_in[0];
    const float* Wx    = (const float*)d_in[1];
    const float* Wh1   = (const float*)d_in[2];
    const float* Wh2   = (const float*)d_in[3];
    const float* bias  = (const float*)d_in[4];
    const float* gamma = (const float*)d_in[5];
    const float* beta  = (const float*)d_in[6];
    float* out = (float*)d_out;

    cudaFuncSetAttribute(mdlstm_persist,
                         cudaFuncAttributeMaxDynamicSharedMemorySize, SMEM_BYTES);

    xp_gemm<<<dim3(Gg / 64, MXP / 128), 256>>>(x, Wx, bias);
    mdlstm_persist<<<NBLK, 256, SMEM_BYTES>>>(Wh1, Wh2);
    bn_reduce1<<<128, 256>>>();
    bn_reduce2<<<1, 256>>>(gamma, beta);
    writeout<<<Bk * Wd, 256>>>(out);
}

// round 12
// speedup vs baseline: 2.1368x; 1.1614x over previous
#include <cuda_runtime.h>
#include <cuda_bf16.h>
#include <math.h>

#define Bk   8
#define Cc   512
#define Wd   64
#define Hd   32
#define HIDd 256
#define Gg   1280
#define WH   (Wd*Hd)        // 2048
#define MXP  (Bk*WH)        // 16384
#define NDIAG (Wd + Hd - 1) // 95
#define NBLK 144            // 16 hid-chunks x 9 row-groups
#define RG   9

// ---- persistent-kernel smem layout (bytes) ----
// Ws hi [80][512] bf16 | Ws lo | A hi [32][512] bf16 | A lo
#define WHI_OFF 0
#define WLO_OFF 81920
#define AHI_OFF 163840
#define ALO_OFF 196608
#define SMEM_P  229376      // <= 232448 opt-in cap

// ---------------- device scratch ----------------
__device__ float g_xp[(size_t)MXP * Gg];
__device__ float g_h [(size_t)WH * Bk * HIDd];      // (w,h,b,hid)
__device__ float g_c [(size_t)WH * Bk * HIDd];
__device__ float g_part[2 * 128 * HIDd];
__device__ float g_scale[HIDd];
__device__ float g_shift[HIDd];
__device__ unsigned g_cnt = 0;
__device__ unsigned g_gen = 0;

// ---------------- helpers ----------------
__device__ __forceinline__ unsigned pk(__nv_bfloat16 a, __nv_bfloat16 b) {
    __nv_bfloat162 t; t.x = a; t.y = b;
    return *(unsigned*)&t;
}
// XOR-swizzled frag load: base = u32 view of a [rows][512 bf16] region (1024B row pitch)
__device__ __forceinline__ unsigned ldfrag(const unsigned* base, int r, int k) {
    unsigned boff = ((unsigned)(k * 2)) ^ (((unsigned)r & 7u) << 4);
    return base[(r << 8) + (boff >> 2)];
}
__device__ __forceinline__ void mma_bf16(float* d, unsigned a0, unsigned a1,
                                         unsigned a2, unsigned a3,
                                         unsigned b0, unsigned b1) {
    asm volatile(
        "mma.sync.aligned.m16n8k16.row.col.f32.bf16.bf16.f32 "
        "{%0,%1,%2,%3}, {%4,%5,%6,%7}, {%8,%9}, {%0,%1,%2,%3};"
        : "+f"(d[0]), "+f"(d[1]), "+f"(d[2]), "+f"(d[3])
        : "r"(a0), "r"(a1), "r"(a2), "r"(a3), "r"(b0), "r"(b1));
}

// ---------------- Kernel A: xp = x @ Wx + b (scalar fp32, proven) ----------------
__global__ __launch_bounds__(256) void xp_gemm(const float* __restrict__ x,
                                               const float* __restrict__ Wx,
                                               const float* __restrict__ bias) {
    __shared__ float As[16][128];
    __shared__ float Bs[16][64];
    const int bm  = blockIdx.y * 128;
    const int bn  = blockIdx.x * 64;
    const int tid = threadIdx.x;

    const int b   = bm >> 11;
    const int wh0 = bm & 2047;
    const float* xb = x + (size_t)b * Cc * WH + wh0;

    const int am  = tid & 127;
    const int ak  = tid >> 7;
    const int bkr = tid >> 4;
    const int bn4 = (tid & 15) * 4;
    const int tx  = tid & 15;
    const int ty  = tid >> 4;

    float acc[8][4];
#pragma unroll
    for (int i = 0; i < 8; i++)
#pragma unroll
        for (int j = 0; j < 4; j++) acc[i][j] = 0.f;

    for (int k0 = 0; k0 < Cc; k0 += 16) {
#pragma unroll
        for (int j = 0; j < 8; j++) {
            int c = ak + j * 2;
            As[c][am] = xb[(size_t)(k0 + c) * WH + am];
        }
        *(float4*)&Bs[bkr][bn4] =
            *(const float4*)&Wx[(size_t)(k0 + bkr) * Gg + bn + bn4];
        __syncthreads();
#pragma unroll
        for (int kk = 0; kk < 16; kk++) {
            float4 a0 = *(float4*)&As[kk][ty * 8];
            float4 a1 = *(float4*)&As[kk][ty * 8 + 4];
            float4 bv = *(float4*)&Bs[kk][tx * 4];
            float aa[8] = {a0.x, a0.y, a0.z, a0.w, a1.x, a1.y, a1.z, a1.w};
            float bb[4] = {bv.x, bv.y, bv.z, bv.w};
#pragma unroll
            for (int i = 0; i < 8; i++)
#pragma unroll
                for (int j = 0; j < 4; j++) acc[i][j] += aa[i] * bb[j];
        }
        __syncthreads();
    }

    float4 bb4 = *(const float4*)&bias[bn + tx * 4];
#pragma unroll
    for (int i = 0; i < 8; i++) {
        int m = bm + ty * 8 + i;
        float4 v;
        v.x = acc[i][0] + bb4.x;
        v.y = acc[i][1] + bb4.y;
        v.z = acc[i][2] + bb4.z;
        v.w = acc[i][3] + bb4.w;
        *(float4*)&g_xp[(size_t)m * Gg + bn + tx * 4] = v;
    }
}

// ---------------- grid-wide software barrier ----------------
__device__ __forceinline__ void gsync() {
    __threadfence();
    __syncthreads();
    if (threadIdx.x == 0) {
        unsigned old = *(volatile unsigned*)&g_gen;
        if (atomicAdd(&g_cnt, 1u) == NBLK - 1) {
            g_cnt = 0;
            __threadfence();
            *(volatile unsigned*)&g_gen = old + 1;
        } else {
            while (*(volatile unsigned*)&g_gen == old) { }
        }
        __threadfence();
    }
    __syncthreads();
}

// ---------------- persistent MD-LSTM recurrence on HMMA (bf16 hi/lo split) ----------------
// Block: nb = bid&15 (16 hid cols = 80 gate cols), rg = bid>>4 (9 row groups).
// Weights smem (once): Ws_hi/lo[n=80][k=512] bf16, XOR-swizzled (16B granule by n&7).
// Per diagonal: A_hi/lo[32][512] bf16 staged from neighbor h (fp32 -> hi/lo).
// 8 warps: wm = (wid&1)*16 (m16 tile), wg = wid>>1 owns n8 tiles {wg, wg+4, wg+8<10}.
// Full K per warp, 3 mma (AhBh+AhBl+AlBh) per (tile,k16).
__global__ __launch_bounds__(256, 1) void mdlstm_mma(const float* __restrict__ Wh1,
                                                     const float* __restrict__ Wh2) {
    extern __shared__ unsigned char smb[];
    __nv_bfloat16* WsHh = (__nv_bfloat16*)(smb + WHI_OFF);
    __nv_bfloat16* WsLh = (__nv_bfloat16*)(smb + WLO_OFF);

    const int tid = threadIdx.x;
    const int bid = blockIdx.x;
    const int nb  = bid & 15;
    const int rg  = bid >> 4;

    // ---- one-time weight preload: fp32 -> bf16 hi/lo, [n][k] swizzled ----
    for (int i = tid; i < 80 * 512; i += 256) {
        int c = i >> 9, k = i & 511;
        int gc = (c >> 4) * 256 + nb * 16 + (c & 15);
        float w = (k < 256) ? Wh1[(size_t)k * Gg + gc]
                            : Wh2[(size_t)(k - 256) * Gg + gc];
        __nv_bfloat16 h = __float2bfloat16(w);
        __nv_bfloat16 l = __float2bfloat16(w - __bfloat162float(h));
        unsigned boff = ((unsigned)(k * 2)) ^ (((unsigned)c & 7u) << 4);
        WsHh[c * 512 + (boff >> 1)] = h;
        WsLh[c * 512 + (boff >> 1)] = l;
    }

    const int lane = tid & 31;
    const int wid  = tid >> 5;
    const int gid  = lane >> 2;        // 0..7
    const int tq   = lane & 3;         // 0..3
    const int wm   = (wid & 1) * 16;
    const int wg   = wid >> 1;
    const int srow = tid >> 3;         // 0..31 staging row
    const int sq   = tid & 7;          // 8 threads per row

    const unsigned* AH = (const unsigned*)(smb + AHI_OFF);
    const unsigned* AL = (const unsigned*)(smb + ALO_OFF);
    const unsigned* BH = (const unsigned*)(smb + WHI_OFF);
    const unsigned* BL = (const unsigned*)(smb + WLO_OFF);

    for (int d = 0; d < NDIAG; d++) {
        int w_lo = d - (Hd - 1); if (w_lo < 0) w_lo = 0;
        int w_hi = (d < Wd - 1) ? d : (Wd - 1);
        int M = (w_hi - w_lo + 1) * Bk;
        int mt2 = (M + RG - 1) / RG;   // rows this block (<=29)
        int r0 = rg * mt2;

        if (r0 < M) {
            // ---- stage A (neighbor h) as bf16 hi/lo, rows 0..31 (pad w/ zeros) ----
            {
                const float* pl = nullptr;
                const float* pu = nullptr;
                int gr = r0 + srow;
                if (srow < mt2 && gr < M) {
                    int ci = gr >> 3, b = gr & 7;
                    int w = w_lo + ci, h = d - w;
                    if (h > 0) pl = g_h + ((size_t)((w * Hd + (h - 1)) * Bk + b)) * HIDd;
                    if (w > 0) pu = g_h + ((size_t)(((w - 1) * Hd + h) * Bk + b)) * HIDd;
                }
#pragma unroll
                for (int j = 0; j < 8; j++) {
                    int kk = (sq + 8 * j) * 8;          // 8 consecutive k
                    const float* src = (j < 4) ? pl : pu;
                    float4 v0 = make_float4(0.f, 0.f, 0.f, 0.f);
                    float4 v1 = v0;
                    if (src) {
                        int ko = (j < 4) ? kk : kk - 256;
                        v0 = *(const float4*)(src + ko);
                        v1 = *(const float4*)(src + ko + 4);
                    }
                    float f[8] = {v0.x, v0.y, v0.z, v0.w, v1.x, v1.y, v1.z, v1.w};
                    __nv_bfloat16 hh[8], ll[8];
#pragma unroll
                    for (int e = 0; e < 8; e++) {
                        hh[e] = __float2bfloat16(f[e]);
                        ll[e] = __float2bfloat16(f[e] - __bfloat162float(hh[e]));
                    }
                    uint4 Hv, Lv;
                    Hv.x = pk(hh[0], hh[1]); Hv.y = pk(hh[2], hh[3]);
                    Hv.z = pk(hh[4], hh[5]); Hv.w = pk(hh[6], hh[7]);
                    Lv.x = pk(ll[0], ll[1]); Lv.y = pk(ll[2], ll[3]);
                    Lv.z = pk(ll[4], ll[5]); Lv.w = pk(ll[6], ll[7]);
                    unsigned boff = ((unsigned)(kk * 2)) ^ (((unsigned)srow & 7u) << 4);
                    *(uint4*)(smb + AHI_OFF + srow * 1024 + boff) = Hv;
                    *(uint4*)(smb + ALO_OFF + srow * 1024 + boff) = Lv;
                }
            }
            __syncthreads();

            // ---- warp-tile mma over full K ----
            int nts[3]; int nn = 0;
            for (int t = wg; t < 10; t += 4) nts[nn++] = t;
            float dd[3][4];
#pragma unroll
            for (int j = 0; j < 3; j++)
#pragma unroll
                for (int e = 0; e < 4; e++) dd[j][e] = 0.f;

            const int ra = wm + gid;
#pragma unroll 2
            for (int k0 = 0; k0 < 512; k0 += 16) {
                int ka = k0 + tq * 2;
                unsigned ah0 = ldfrag(AH, ra,     ka);
                unsigned ah1 = ldfrag(AH, ra + 8, ka);
                unsigned ah2 = ldfrag(AH, ra,     ka + 8);
                unsigned ah3 = ldfrag(AH, ra + 8, ka + 8);
                unsigned al0 = ldfrag(AL, ra,     ka);
                unsigned al1 = ldfrag(AL, ra + 8, ka);
                unsigned al2 = ldfrag(AL, ra,     ka + 8);
                unsigned al3 = ldfrag(AL, ra + 8, ka + 8);
                for (int j = 0; j < nn; j++) {
                    int nr = nts[j] * 8 + gid;
                    unsigned bh0 = ldfrag(BH, nr, ka);
                    unsigned bh1 = ldfrag(BH, nr, ka + 8);
                    unsigned bl0 = ldfrag(BL, nr, ka);
                    unsigned bl1 = ldfrag(BL, nr, ka + 8);
                    mma_bf16(dd[j], ah0, ah1, ah2, ah3, bh0, bh1);
                    mma_bf16(dd[j], ah0, ah1, ah2, ah3, bl0, bl1);
                    mma_bf16(dd[j], al0, al1, al2, al3, bh0, bh1);
                }
            }

            // ---- gather D frags to smem (overlay on A region) ----
            __syncthreads();           // everyone done reading A
            float* Gs = (float*)(smb + AHI_OFF);   // [32][84]
            for (int j = 0; j < nn; j++) {
                int c0 = nts[j] * 8 + tq * 2;
                *(float2*)&Gs[(wm + gid) * 84 + c0]     = make_float2(dd[j][0], dd[j][1]);
                *(float2*)&Gs[(wm + gid + 8) * 84 + c0] = make_float2(dd[j][2], dd[j][3]);
            }
            __syncthreads();

            // ---- fused LSTM pointwise ----
#pragma unroll
            for (int pass = 0; pass < 2; pass++) {
                int r = (tid >> 4) + pass * 16;
                int hidx = tid & 15;
                if (r < mt2) {
                    int gr = r0 + r;
                    if (gr < M) {
                        int ci = gr >> 3, b = gr & 7;
                        int w = w_lo + ci, h = d - w;
                        const int hid = nb * 16 + hidx;

                        const float* xg = g_xp + ((size_t)(b * WH + w * Hd + h)) * Gg;
                        float gi  = Gs[r * 84 +   0 + hidx] + xg[hid];
                        float gf1 = Gs[r * 84 +  16 + hidx] + xg[HIDd + hid];
                        float gf2 = Gs[r * 84 +  32 + hidx] + xg[2 * HIDd + hid];
                        float go  = Gs[r * 84 +  48 + hidx] + xg[3 * HIDd + hid];
                        float gc  = Gs[r * 84 +  64 + hidx] + xg[4 * HIDd + hid];

                        float i_ = 1.f / (1.f + expf(-gi));
                        float f1 = 1.f / (1.f + expf(-gf1));
                        float f2 = 1.f / (1.f + expf(-gf2));
                        float o_ = 1.f / (1.f + expf(-go));
                        float cand = tanhf(gc);

                        float cl = (h > 0) ? g_c[((size_t)((w * Hd + (h - 1)) * Bk + b)) * HIDd + hid] : 0.f;
                        float cu = (w > 0) ? g_c[((size_t)(((w - 1) * Hd + h) * Bk + b)) * HIDd + hid] : 0.f;

                        float cc = i_ * cand + f1 * cl + f2 * cu;
                        float hv = o_ * tanhf(cc);

                        size_t oidx = ((size_t)((w * Hd + h) * Bk + b)) * HIDd + hid;
                        g_c[oidx] = cc;
                        g_h[oidx] = hv;
                    }
                }
            }
        }

        gsync();
    }
}

// ---------------- BN stats ----------------
__global__ __launch_bounds__(256) void bn_reduce1() {
    const int t = threadIdx.x;
    const size_t r0 = (size_t)blockIdx.x * 128;
    float s = 0.f, s2 = 0.f;
    for (int r = 0; r < 128; r++) {
        float v = g_h[(r0 + r) * HIDd + t];
        s += v;
        s2 += v * v;
    }
    g_part[blockIdx.x * HIDd + t] = s;
    g_part[128 * HIDd + blockIdx.x * HIDd + t] = s2;
}

__global__ __launch_bounds__(256) void bn_reduce2(const float* __restrict__ gamma,
                                                  const float* __restrict__ beta) {
    const int t = threadIdx.x;
    float s0 = 0.f, s1 = 0.f, q0 = 0.f, q1 = 0.f;
#pragma unroll 4
    for (int i = 0; i < 128; i += 2) {
        s0 += g_part[i * HIDd + t];
        s1 += g_part[(i + 1) * HIDd + t];
        q0 += g_part[128 * HIDd + i * HIDd + t];
        q1 += g_part[128 * HIDd + (i + 1) * HIDd + t];
    }
    float s = s0 + s1, s2 = q0 + q1;
    const float invn = 1.f / (float)MXP;
    float mean = s * invn;
    float var  = s2 * invn - mean * mean;
    float sc   = gamma[t] * rsqrtf(var + 1e-5f);
    g_scale[t] = sc;
    g_shift[t] = beta[t] - mean * sc;
}

// ---------------- final writeout (smem transpose, coalesced both sides) ----------------
__global__ __launch_bounds__(256) void writeout(float* __restrict__ out) {
    __shared__ float t[32][257];
    const int bw = blockIdx.x;
    const int b  = bw >> 6;
    const int w  = bw & 63;
    const int tid = threadIdx.x;
    const int ch8 = tid >> 5;
    const int hl  = tid & 31;

    for (int hh = 0; hh < 32; hh++)
        t[hh][tid] = g_h[((size_t)((w * Hd + hh) * Bk + b)) * HIDd + tid];
    __syncthreads();
    for (int c0 = 0; c0 < 256; c0 += 8) {
        int ch = c0 + ch8;
        float v = t[hl][ch];
        size_t oi = (((size_t)b * HIDd + ch) * Wd + w) * Hd + hl;
        out[oi] = tanhf(v * g_scale[ch] + g_shift[ch]);
        out[(size_t)MXP * HIDd + oi] = v;
    }
    __syncthreads();

    for (int hh = 0; hh < 32; hh++)
        t[hh][tid] = g_c[((size_t)((w * Hd + hh) * Bk + b)) * HIDd + tid];
    __syncthreads();
    for (int c0 = 0; c0 < 256; c0 += 8) {
        int ch = c0 + ch8;
        size_t oi = (((size_t)b * HIDd + ch) * Wd + w) * Hd + hl;
        out[(size_t)2 * MXP * HIDd + oi] = t[hl][ch];
    }
}

// ---------------- launch ----------------
extern "C" void kernel_launch(void* const* d_in, const int* in_sizes, int n_in,
                              void* d_out, int out_size) {
    const float* x     = (const float*)d_in[0];
    const float* Wx    = (const float*)d_in[1];
    const float* Wh1   = (const float*)d_in[2];
    const float* Wh2   = (const float*)d_in[3];
    const float* bias  = (const float*)d_in[4];
    const float* gamma = (const float*)d_in[5];
    const float* beta  = (const float*)d_in[6];
    float* out = (float*)d_out;

    cudaFuncSetAttribute(mdlstm_mma,
                         cudaFuncAttributeMaxDynamicSharedMemorySize, SMEM_P);

    xp_gemm<<<dim3(Gg / 64, MXP / 128), 256>>>(x, Wx, bias);
    mdlstm_mma<<<NBLK, 256, SMEM_P>>>(Wh1, Wh2);
    bn_reduce1<<<128, 256>>>();
    bn_reduce2<<<1, 256>>>(gamma, beta);
    writeout<<<Bk * Wd, 256>>>(out);
}